// round 15
// baseline (speedup 1.0000x reference)
#include <cuda_runtime.h>

// out = clamp(floor(x * 16 + r) * (1/16), -8.0, 7.9375)
// WL=8, FL=4 -> sigma = 2^-4 (power of 2: *16 and *0.0625 are exact in fp32).
//
// HBM-roofline streaming kernel, reproducibly at ~7.2 TB/s (90% of spec).
// Knob history: linear float4 stream wins; cache hints neutral; unroll x2
// negative (both global-split and block-local); block 512 > 256.
// This round samples the last point on the block-size axis: 1024 thr/block
// (32768 CTAs, fewer scheduling events / wave transitions). Everything else
// identical to the 225.5us best.

__device__ __forceinline__ float quant1(float x, float r) {
    float q = floorf(fmaf(x, 16.0f, r)) * 0.0625f;
    q = fminf(q, 7.9375f);
    q = fmaxf(q, -8.0f);
    return q;
}

__global__ void __launch_bounds__(1024) quant_kernel_v4(
    const float4* __restrict__ x,
    const float4* __restrict__ r,
    float4* __restrict__ out,
    int n4)
{
    int i = blockIdx.x * blockDim.x + threadIdx.x;
    if (i < n4) {
        float4 xv = x[i];
        float4 rv = r[i];
        float4 o;
        o.x = quant1(xv.x, rv.x);
        o.y = quant1(xv.y, rv.y);
        o.z = quant1(xv.z, rv.z);
        o.w = quant1(xv.w, rv.w);
        out[i] = o;
    }
}

__global__ void quant_kernel_tail(
    const float* __restrict__ x,
    const float* __restrict__ r,
    float* __restrict__ out,
    int start, int n)
{
    int i = start + blockIdx.x * blockDim.x + threadIdx.x;
    if (i < n) out[i] = quant1(x[i], r[i]);
}

extern "C" void kernel_launch(void* const* d_in, const int* in_sizes, int n_in,
                              void* d_out, int out_size) {
    const float* x = (const float*)d_in[0];
    const float* r = (const float*)d_in[1];
    float* out = (float*)d_out;
    int n = in_sizes[0];

    int n4 = n / 4;
    if (n4 > 0) {
        const int threads = 1024;
        int blocks = (n4 + threads - 1) / threads;  // exact: 32768 for n=2^27
        quant_kernel_v4<<<blocks, threads>>>(
            (const float4*)x, (const float4*)r, (float4*)out, n4);
    }
    int rem_start = n4 * 4;
    int rem = n - rem_start;
    if (rem > 0) {
        quant_kernel_tail<<<(rem + 255) / 256, 256>>>(x, r, out, rem_start, n);
    }
}

// round 16
// speedup vs baseline: 1.0106x; 1.0106x over previous
#include <cuda_runtime.h>

// out = clamp(floor(x * 16 + r) * (1/16), -8.0, 7.9375)
// WL=8, FL=4 -> sigma = 2^-4 (power of 2: *16 and *0.0625 are exact in fp32).
//
// FINAL converged HBM-roofline kernel: ~7.2 TB/s (90% of 8 TB/s spec),
// DRAM-pct 90.8, all compute pipes idle, rel_err 0.0.
// Full knob enumeration (all measured on GB300):
//   - access pattern: single linear float4 stream wins (split/unrolled worse)
//   - cache hints (__ldcs/__stcs): neutral
//   - unroll x2: negative (both global-split and block-local forms)
//   - block size: 512 best (256 -> 227.4us, 512 -> 225.5us, 1024 -> 226.0us)
// Traffic is mandatory (2 reads + 1 write x 512 MB fp32); nothing left to cut.

__device__ __forceinline__ float quant1(float x, float r) {
    float q = floorf(fmaf(x, 16.0f, r)) * 0.0625f;
    q = fminf(q, 7.9375f);
    q = fmaxf(q, -8.0f);
    return q;
}

__global__ void __launch_bounds__(512) quant_kernel_v4(
    const float4* __restrict__ x,
    const float4* __restrict__ r,
    float4* __restrict__ out,
    int n4)
{
    int i = blockIdx.x * blockDim.x + threadIdx.x;
    if (i < n4) {
        float4 xv = x[i];
        float4 rv = r[i];
        float4 o;
        o.x = quant1(xv.x, rv.x);
        o.y = quant1(xv.y, rv.y);
        o.z = quant1(xv.z, rv.z);
        o.w = quant1(xv.w, rv.w);
        out[i] = o;
    }
}

__global__ void quant_kernel_tail(
    const float* __restrict__ x,
    const float* __restrict__ r,
    float* __restrict__ out,
    int start, int n)
{
    int i = start + blockIdx.x * blockDim.x + threadIdx.x;
    if (i < n) out[i] = quant1(x[i], r[i]);
}

extern "C" void kernel_launch(void* const* d_in, const int* in_sizes, int n_in,
                              void* d_out, int out_size) {
    const float* x = (const float*)d_in[0];
    const float* r = (const float*)d_in[1];
    float* out = (float*)d_out;
    int n = in_sizes[0];

    int n4 = n / 4;
    if (n4 > 0) {
        const int threads = 512;
        int blocks = (n4 + threads - 1) / threads;  // exact: 65536 for n=2^27
        quant_kernel_v4<<<blocks, threads>>>(
            (const float4*)x, (const float4*)r, (float4*)out, n4);
    }
    int rem_start = n4 * 4;
    int rem = n - rem_start;
    if (rem > 0) {
        quant_kernel_tail<<<(rem + 255) / 256, 256>>>(x, r, out, rem_start, n);
    }
}